// round 17
// baseline (speedup 1.0000x reference)
#include <cuda_runtime.h>
#include <cuda_fp16.h>
#include <cstdint>
#include <math.h>

#define BATCH   4
#define NSEQ    4096
#define DIM     512
#define MTOT    (BATCH*NSEQ)   // 16384
#define NBT     32             // N column tiles per batch in scores GEMM

// tile counts for the persistent scheduler
#define NT_QKV  1536           // 12 x 128
#define NT_SC   4096           // 32 x 32 x 4
#define NT_PV   512            // 4 x 32 x 4
#define NT_TOT  (NT_QKV + NT_SC + NT_PV)

// ---------------- scratch (allocation-free rule: device globals) ----------------
__device__ __align__(256) __half g_x16[(size_t)MTOT*DIM];
__device__ __align__(256) __half g_w16[3*DIM*DIM];   // [wq;wk;wv] = [1536,512]
__device__ __align__(256) __half g_Q [(size_t)MTOT*DIM];
__device__ __align__(256) __half g_K [(size_t)MTOT*DIM];
__device__ __align__(256) __half g_Vt[(size_t)BATCH*DIM*NSEQ];
__device__ __align__(256) __half g_P [(size_t)BATCH*NSEQ*NSEQ];   // unnormalized exp(S)
__device__ __align__(256) float  g_ps[(size_t)BATCH*NBT*NSEQ];    // per-tile row partial sums
__device__ int g_ticket;
__device__ int g_qkvDone;
__device__ int g_scDone[BATCH];

// ---------------- helpers (plain sm_80-level PTX: valid on sm_103 target) -------
__device__ __forceinline__ uint32_t smem_to_u32(const void* p) {
    uint32_t a;
    asm("{ .reg .u64 t; cvta.to.shared.u64 t, %1; cvt.u32.u64 %0, t; }" : "=r"(a) : "l"(p));
    return a;
}
__device__ __forceinline__ void cp16(uint32_t dst, const void* src) {
    asm volatile("cp.async.cg.shared.global [%0], [%1], 16;" :: "r"(dst), "l"(src));
}
#define CP_COMMIT() asm volatile("cp.async.commit_group;")
#define CP_WAIT1()  asm volatile("cp.async.wait_group 1;")

#define LDSM_X4(r0,r1,r2,r3, addr) \
    asm volatile("ldmatrix.sync.aligned.m8n8.x4.shared.b16 {%0,%1,%2,%3}, [%4];" \
        : "=r"(r0), "=r"(r1), "=r"(r2), "=r"(r3) : "r"(addr))

#define MMA16816(d, a, b0, b1) \
    asm volatile("mma.sync.aligned.m16n8k16.row.col.f32.f16.f16.f32 " \
        "{%0,%1,%2,%3}, {%4,%5,%6,%7}, {%8,%9}, {%0,%1,%2,%3};" \
        : "+f"((d)[0]), "+f"((d)[1]), "+f"((d)[2]), "+f"((d)[3]) \
        : "r"((a)[0]), "r"((a)[1]), "r"((a)[2]), "r"((a)[3]), "r"(b0), "r"(b1))

#define MMA16816F16(d, a, b0, b1) \
    asm volatile("mma.sync.aligned.m16n8k16.row.col.f16.f16.f16.f16 " \
        "{%0,%1}, {%2,%3,%4,%5}, {%6,%7}, {%0,%1};" \
        : "+r"((d)[0]), "+r"((d)[1]) \
        : "r"((a)[0]), "r"((a)[1]), "r"((a)[2]), "r"((a)[3]), "r"(b0), "r"(b1))

// 16B-chunk XOR swizzle for [rows][64 half] tiles (128B rows, 8 chunks/row)
__device__ __forceinline__ uint32_t swz(int r, int c) {
    return (uint32_t)(r * 128 + ((c ^ (r & 7)) << 4));
}

#define STAGES      3
#define STAGE_BYTES 32768   // A 16KB + B 16KB
#define SMEM_DYN    (STAGES * STAGE_BYTES)
#define SMEM_DYN_RI (SMEM_DYN + 512)

// ---------------------------------------------------------------------------
// One 128x128 GEMM tile (the round-16 mma_gemm body, blockIdx -> args).
// BK=64, 3-stage cp.async pipeline, 4 warps (2m x 2n), 64x64 warp tiles,
// 2-deep register fragment pipeline.
// EPI 5: fused QKV routing (fp32 acc), EPI 3: exp+partial sums (fp16 acc),
// EPI 4: row-normalized fp32 out, ri computed in pipeline-fill shadow.
// ---------------------------------------------------------------------------
template<int EPI, bool ACC16>
__device__ __forceinline__
void gemm_tile(const __half* __restrict__ A, const __half* __restrict__ B,
               int K, size_t sA, size_t sB, float scale,
               float* __restrict__ Cf, __half* __restrict__ Ch,
               size_t sC, int ldC, float* __restrict__ aux,
               int bx, int by, int z, char* smem)
{
    const uint32_t sm0 = smem_to_u32(smem);
    const int tid  = threadIdx.x;
    const int lane = tid & 31;
    const int wid  = tid >> 5;
    const int wm   = wid & 1;
    const int wn   = wid >> 1;
    const int bm   = by * 128;
    const int bn   = bx * 128;

    const __half* Ap0 = A + (size_t)z * sA + (size_t)bm * K;
    const __half* Bp0 = B + (size_t)z * sB + (size_t)bn * K;

    const int NCH = K >> 6;

    float    acc[ACC16 ? 1 : 4][8][4];
    uint32_t a16[ACC16 ? 4 : 1][8][2];
    if constexpr (!ACC16) {
        #pragma unroll
        for (int i = 0; i < 4; i++)
            #pragma unroll
            for (int j = 0; j < 8; j++)
                #pragma unroll
                for (int e = 0; e < 4; e++) acc[i][j][e] = 0.f;
    } else {
        #pragma unroll
        for (int i = 0; i < 4; i++)
            #pragma unroll
            for (int j = 0; j < 8; j++) { a16[i][j][0] = 0u; a16[i][j][1] = 0u; }
    }

    auto issue = [&](int i, int s) {
        const __half* Ap = Ap0 + (i << 6);
        const __half* Bp = Bp0 + (i << 6);
        uint32_t sa = sm0 + (uint32_t)s * STAGE_BYTES;
        #pragma unroll
        for (int u = 0; u < 8; u++) {
            int id = tid + u * 128;
            int r  = id >> 3;
            int c  = id & 7;
            uint32_t sw = swz(r, c);
            cp16(sa + sw,         Ap + (size_t)r * K + c * 8);
            cp16(sa + 16384 + sw, Bp + (size_t)r * K + c * 8);
        }
        CP_COMMIT();
    };

    auto ldfrag = [&](uint32_t (*fa)[4], uint32_t (*fb)[4], uint32_t sa, int ks) {
        #pragma unroll
        for (int mi = 0; mi < 4; mi++) {
            int r = wm * 64 + mi * 16 + (lane & 15);
            int c = 2 * ks + (lane >> 4);
            LDSM_X4(fa[mi][0], fa[mi][1], fa[mi][2], fa[mi][3], sa + swz(r, c));
        }
        #pragma unroll
        for (int g = 0; g < 4; g++) {
            int n = wn * 64 + g * 16 + (lane & 7) + ((lane >> 4) & 1) * 8;
            int c = 2 * ks + ((lane >> 3) & 1);
            LDSM_X4(fb[g][0], fb[g][1], fb[g][2], fb[g][3], sa + 16384 + swz(n, c));
        }
    };

    auto mma_all = [&](uint32_t (*fa)[4], uint32_t (*fb)[4]) {
        #pragma unroll
        for (int mi = 0; mi < 4; mi++)
            #pragma unroll
            for (int ni = 0; ni < 8; ni++) {
                if constexpr (ACC16)
                    MMA16816F16(a16[mi][ni], fa[mi],
                                fb[ni >> 1][(ni & 1) * 2], fb[ni >> 1][(ni & 1) * 2 + 1]);
                else
                    MMA16816(acc[mi][ni], fa[mi],
                             fb[ni >> 1][(ni & 1) * 2], fb[ni >> 1][(ni & 1) * 2 + 1]);
            }
    };

    uint32_t fa[2][4][4], fb[2][4][4];

    issue(0, 0);
    issue(1, 1);

    if constexpr (EPI == 4) {   // fused rowinv in the pipeline-fill shadow
        float* ris = (float*)(smem + SMEM_DYN);
        const float* p = aux + (size_t)z * (NBT * NSEQ) + bm + tid;
        float s = 0.f;
        #pragma unroll
        for (int i = 0; i < NBT; i++) s += p[(size_t)i * NSEQ];
        ris[tid] = 1.0f / s;
    }

    CP_WAIT1();
    __syncthreads();
    ldfrag(fa[0], fb[0], sm0, 0);

    for (int i = 0; i < NCH; i++) {
        uint32_t sa = sm0 + (uint32_t)(i % STAGES) * STAGE_BYTES;
        ldfrag(fa[1], fb[1], sa, 1);
        if (i + 2 < NCH) issue(i + 2, (i + 2) % STAGES); else CP_COMMIT();
        mma_all(fa[0], fb[0]);          // ks 0
        ldfrag(fa[0], fb[0], sa, 2);
        mma_all(fa[1], fb[1]);          // ks 1
        ldfrag(fa[1], fb[1], sa, 3);
        mma_all(fa[0], fb[0]);          // ks 2
        CP_WAIT1();
        __syncthreads();
        if (i + 1 < NCH)
            ldfrag(fa[0], fb[0], sm0 + (uint32_t)((i + 1) % STAGES) * STAGE_BYTES, 0);
        mma_all(fa[1], fb[1]);          // ks 3
    }

    if constexpr (EPI == 5) {     // fused QKV routing
        const int sect = bn >> 9;
        #pragma unroll
        for (int mi = 0; mi < 4; mi++) {
            int row0 = bm + wm * 64 + mi * 16 + (lane >> 2);
            #pragma unroll
            for (int ni = 0; ni < 8; ni++) {
                int colg = bn + wn * 64 + ni * 8 + (lane & 3) * 2;
                int c    = colg & 511;
                if (sect == 0) {
                    __half2 h0 = __floats2half2_rn(acc[mi][ni][0] * scale, acc[mi][ni][1] * scale);
                    __half2 h1 = __floats2half2_rn(acc[mi][ni][2] * scale, acc[mi][ni][3] * scale);
                    *(__half2*)(g_Q + (size_t)row0       * DIM + c) = h0;
                    *(__half2*)(g_Q + (size_t)(row0 + 8) * DIM + c) = h1;
                } else if (sect == 1) {
                    __half2 h0 = __floats2half2_rn(acc[mi][ni][0], acc[mi][ni][1]);
                    __half2 h1 = __floats2half2_rn(acc[mi][ni][2], acc[mi][ni][3]);
                    *(__half2*)(g_K + (size_t)row0       * DIM + c) = h0;
                    *(__half2*)(g_K + (size_t)(row0 + 8) * DIM + c) = h1;
                } else {
                    #pragma unroll
                    for (int e = 0; e < 4; e++) {
                        int m  = row0 + (e >> 1) * 8;
                        int cc = c + (e & 1);
                        int b  = m >> 12;
                        int sq = m & (NSEQ - 1);
                        g_Vt[(size_t)b * DIM * NSEQ + (size_t)cc * NSEQ + sq] =
                            __float2half(acc[mi][ni][e]);
                    }
                }
            }
        }
    } else if constexpr (EPI == 3) {   // exp + per-tile row partial sums
        __half* Cz = Ch + (size_t)z * sC;
        float rs[4][2] = {};
        #pragma unroll
        for (int mi = 0; mi < 4; mi++) {
            int row0 = bm + wm * 64 + mi * 16 + (lane >> 2);
            #pragma unroll
            for (int ni = 0; ni < 8; ni++) {
                int col = bn + wn * 64 + ni * 8 + (lane & 3) * 2;
                float2 f0 = __half22float2(*(__half2*)&a16[mi][ni][0]);
                float2 f1 = __half22float2(*(__half2*)&a16[mi][ni][1]);
                float e0 = __expf(f0.x * scale);
                float e1 = __expf(f0.y * scale);
                float e2 = __expf(f1.x * scale);
                float e3 = __expf(f1.y * scale);
                *(__half2*)(Cz + (size_t)row0       * ldC + col) = __floats2half2_rn(e0, e1);
                *(__half2*)(Cz + (size_t)(row0 + 8) * ldC + col) = __floats2half2_rn(e2, e3);
                rs[mi][0] += e0 + e1;
                rs[mi][1] += e2 + e3;
            }
        }
        __syncthreads();                 // stage smem -> psm overlay
        float* psm = (float*)smem;
        #pragma unroll
        for (int mi = 0; mi < 4; mi++)
            #pragma unroll
            for (int h = 0; h < 2; h++) {
                float t = rs[mi][h];
                t += __shfl_xor_sync(0xffffffffu, t, 1);
                t += __shfl_xor_sync(0xffffffffu, t, 2);
                if ((lane & 3) == 0)
                    psm[wn * 128 + wm * 64 + mi * 16 + (lane >> 2) + h * 8] = t;
            }
        __syncthreads();
        if (tid < 128) {
            float t = psm[tid] + psm[128 + tid];
            aux[(size_t)z * (NBT * NSEQ) + (size_t)bx * NSEQ + bm + tid] = t;
        }
    } else {                      // EPI == 4: fp32 out, row-normalized
        float* base = Cf + (size_t)z * sC;
        const float* ris = (const float*)(smem + SMEM_DYN);
        #pragma unroll
        for (int mi = 0; mi < 4; mi++) {
            int r0 = wm * 64 + mi * 16 + (lane >> 2);
            int row0 = bm + r0;
            float i0 = ris[r0];
            float i1 = ris[r0 + 8];
            #pragma unroll
            for (int ni = 0; ni < 8; ni++) {
                int col = bn + wn * 64 + ni * 8 + (lane & 3) * 2;
                *(float2*)(base + (size_t)row0       * ldC + col) =
                    make_float2(acc[mi][ni][0] * i0, acc[mi][ni][1] * i0);
                *(float2*)(base + (size_t)(row0 + 8) * ldC + col) =
                    make_float2(acc[mi][ni][2] * i1, acc[mi][ni][3] * i1);
            }
        }
    }
}

// ---------------------------------------------------------------------------
// Persistent mega-kernel: ticket scheduler over QKV -> scores -> PV tiles.
// Dependencies via fence-protected counters; deadlock-free because every
// awaited phase's tickets precede the waiter's ticket (resident CTAs that
// hold those tickets are running, not spinning).
// ---------------------------------------------------------------------------
__global__ __launch_bounds__(128, 2)
void mega(float* __restrict__ out)
{
    extern __shared__ __align__(1024) char smem[];
    __shared__ int s_ticket;
    const int tid = threadIdx.x;
    const float inv_sqrt_d = 0.04419417382415922f;  // 1/sqrt(512)

    for (;;) {
        __syncthreads();                       // protect s_ticket reuse
        if (tid == 0) s_ticket = atomicAdd(&g_ticket, 1);
        __syncthreads();
        const int t = s_ticket;
        if (t >= NT_TOT) return;

        if (t < NT_QKV) {
            // QKV tile: bx in [0,12), by in [0,128)
            gemm_tile<5, false>(g_x16, g_w16, DIM, 0, 0, inv_sqrt_d,
                                nullptr, nullptr, 0, 0, nullptr,
                                t % 12, t / 12, 0, smem);
            __threadfence();
            __syncthreads();
            if (tid == 0) atomicAdd(&g_qkvDone, 1);
        } else if (t < NT_QKV + NT_SC) {
            const int u  = t - NT_QKV;
            const int z  = u >> 10;            // batch-major
            const int by = (u >> 5) & 31;
            const int bx = u & 31;
            if (tid == 0) {
                while (*(volatile int*)&g_qkvDone < NT_QKV) { }
                __threadfence();
            }
            __syncthreads();
            gemm_tile<3, true>(g_Q, g_K, DIM,
                               (size_t)NSEQ * DIM, (size_t)NSEQ * DIM, 1.0f,
                               nullptr, g_P, (size_t)NSEQ * NSEQ, NSEQ, g_ps,
                               bx, by, z, smem);
            __threadfence();
            __syncthreads();
            if (tid == 0) atomicAdd(&g_scDone[z], 1);
        } else {
            const int u  = t - NT_QKV - NT_SC;
            const int z  = u >> 7;             // batch-major
            const int by = (u & 127) >> 2;
            const int bx = u & 3;
            if (tid == 0) {
                while (*(volatile int*)&g_scDone[z] < NT_SC / BATCH) { }
                __threadfence();
            }
            __syncthreads();
            gemm_tile<4, false>(g_P, g_Vt, NSEQ,
                                (size_t)NSEQ * NSEQ, (size_t)DIM * NSEQ, 1.0f,
                                out, nullptr, (size_t)NSEQ * DIM, DIM, g_ps,
                                bx, by, z, smem);
        }
    }
}

// ---------------------------------------------------------------------------
// Single fused fp32 -> fp16 convert for x + 3 weight tensors; also resets
// the persistent scheduler's counters (runs before mega on the same stream).
// ---------------------------------------------------------------------------
__global__ __launch_bounds__(256)
void cvt_all(const float* __restrict__ x,
             const float* __restrict__ w0, const float* __restrict__ w1,
             const float* __restrict__ w2,
             __half* __restrict__ ox, __half* __restrict__ ow,
             int nx, int nw)
{
    if (blockIdx.x == 0 && threadIdx.x == 0) {
        g_ticket = 0;
        g_qkvDone = 0;
        #pragma unroll
        for (int b = 0; b < BATCH; b++) g_scDone[b] = 0;
    }
    int i = (blockIdx.x * 256 + threadIdx.x) * 4;
    if (i < nx) {
        float4 v = *(const float4*)(x + i);
        *(__half2*)(ox + i)     = __floats2half2_rn(v.x, v.y);
        *(__half2*)(ox + i + 2) = __floats2half2_rn(v.z, v.w);
    } else {
        int k = i - nx;
        const float* s = (k < nw) ? w0 : (k < 2 * nw) ? w1 : w2;
        int jj = k - ((k < nw) ? 0 : (k < 2 * nw) ? nw : 2 * nw);
        float4 v = *(const float4*)(s + jj);
        *(__half2*)(ow + k)     = __floats2half2_rn(v.x, v.y);
        *(__half2*)(ow + k + 2) = __floats2half2_rn(v.z, v.w);
    }
}

// ---------------------------------------------------------------------------
extern "C" void kernel_launch(void* const* d_in, const int* in_sizes, int n_in,
                              void* d_out, int out_size)
{
    const float* x  = (const float*)d_in[0];
    const float* wq = (const float*)d_in[1];
    const float* wk = (const float*)d_in[2];
    const float* wv = (const float*)d_in[3];
    float* out = (float*)d_out;

    __half *x16, *w16;
    cudaGetSymbolAddress((void**)&x16, g_x16);
    cudaGetSymbolAddress((void**)&w16, g_w16);

    cudaFuncSetAttribute(mega, cudaFuncAttributeMaxDynamicSharedMemorySize, SMEM_DYN_RI);

    const int NX = MTOT * DIM;      // 8388608
    const int NW = DIM * DIM;       // 262144

    cvt_all<<<(NX + 3 * NW) / 1024, 256>>>(x, wq, wk, wv, x16, w16, NX, NW);

    int nsm = 148;
    cudaDeviceGetAttribute(&nsm, cudaDevAttrMultiProcessorCount, 0);

    mega<<<2 * nsm, 128, SMEM_DYN_RI>>>(out);
}